// round 3
// baseline (speedup 1.0000x reference)
#include <cuda_runtime.h>
#include <math.h>

#define N_TOTAL 16384
#define TPB     1024
#define GRID    148
#define ROWS    8

__device__ float        g_partial[GRID];
__device__ unsigned int g_arrive = 0;   // reset by last block each launch

// ---------------------------------------------------------------------------
// Single fused persistent kernel.
//  phase 1: per-block deterministic compaction of pos/neg scores into smem
//  phase 2: pairwise |x| sum via 2x FFMA-imm per pair (rt=1 fma-pipe path)
//           using max(0,x) = (x+|x|)/2, u = x/2:
//             u   = fma(n, 0.5, ch)         ch = 0.5 - 0.5*p
//             acc = fma(|u|, 2.0, acc)      accumulates |x|
//  phase 3: last block computes the linear closed form in double + finalizes
// ---------------------------------------------------------------------------
__global__ __launch_bounds__(TPB, 1)
void fused_kernel(const int* __restrict__ yt, const float* __restrict__ yp,
                  float* __restrict__ out) {
    extern __shared__ float sm[];         // [0,nneg): negs  [nneg,N): pos
    __shared__ int    wsum[32];
    __shared__ float  s_red[32];
    __shared__ double s_dp[32];
    __shared__ double s_dn[32];
    __shared__ int    s_amlast;

    const int tid  = threadIdx.x;
    const int lane = tid & 31;
    const int warp = tid >> 5;

    // ---- phase 1a: load + count pos (E = 16 contiguous elems / thread) ----
    const int E    = N_TOTAL / TPB;       // 16
    const int base = tid * E;
    int4   tt[E / 4];
    float4 vv[E / 4];
    int cp = 0;
    #pragma unroll
    for (int k = 0; k < E / 4; k++) {
        tt[k] = ((const int4*)yt)[(base >> 2) + k];
        vv[k] = ((const float4*)yp)[(base >> 2) + k];
        cp += (tt[k].x == 1) + (tt[k].y == 1) + (tt[k].z == 1) + (tt[k].w == 1);
    }

    // ---- phase 1b: block exclusive scan (deterministic) ----
    int inc = cp;
    #pragma unroll
    for (int o = 1; o < 32; o <<= 1) {
        int t = __shfl_up_sync(0xffffffffu, inc, o);
        if (lane >= o) inc += t;
    }
    if (lane == 31) wsum[warp] = inc;
    __syncthreads();
    if (warp == 0) {
        int w = wsum[lane];
        #pragma unroll
        for (int o = 1; o < 32; o <<= 1) {
            int t = __shfl_up_sync(0xffffffffu, w, o);
            if (lane >= o) w += t;
        }
        wsum[lane] = w;
    }
    __syncthreads();

    const int excl = inc - cp + (warp > 0 ? wsum[warp - 1] : 0);
    const int npos = wsum[31];
    const int nneg = N_TOTAL - npos;
    float* sneg = sm;
    float* spos = sm + nneg;

    // ---- phase 1c: scatter compacted values into smem ----
    {
        int po = excl;
        int no = base - excl;
        #pragma unroll
        for (int k = 0; k < E / 4; k++) {
            if (tt[k].x == 1) spos[po++] = vv[k].x; else sneg[no++] = vv[k].x;
            if (tt[k].y == 1) spos[po++] = vv[k].y; else sneg[no++] = vv[k].y;
            if (tt[k].z == 1) spos[po++] = vv[k].z; else sneg[no++] = vv[k].z;
            if (tt[k].w == 1) spos[po++] = vv[k].w; else sneg[no++] = vv[k].w;
        }
    }
    __syncthreads();

    // ---- phase 2: pairwise |x| sum over this block's contiguous pos chunk --
    const int r_beg = (int)(((long long)npos * blockIdx.x) / GRID);
    const int r_end = (int)(((long long)npos * (blockIdx.x + 1)) / GRID);
    const int nneg4 = nneg & ~3;

    float accv = 0.f;
    int r0 = r_beg;
    for (; r0 + ROWS <= r_end; r0 += ROWS) {
        float ch[ROWS], acc[ROWS];
        #pragma unroll
        for (int r = 0; r < ROWS; r++) {
            ch[r]  = __fmaf_rn(spos[r0 + r], -0.5f, 0.5f);   // FFMA-imm
            acc[r] = 0.f;
        }
        for (int j = tid * 4; j < nneg4; j += TPB * 4) {
            const float4 n4 = *reinterpret_cast<const float4*>(sneg + j);
            #pragma unroll
            for (int r = 0; r < ROWS; r++) {
                float u0 = __fmaf_rn(n4.x, 0.5f, ch[r]);
                float u1 = __fmaf_rn(n4.y, 0.5f, ch[r]);
                float u2 = __fmaf_rn(n4.z, 0.5f, ch[r]);
                float u3 = __fmaf_rn(n4.w, 0.5f, ch[r]);
                acc[r] = __fmaf_rn(fabsf(u0), 2.0f, acc[r]);
                acc[r] = __fmaf_rn(fabsf(u1), 2.0f, acc[r]);
                acc[r] = __fmaf_rn(fabsf(u2), 2.0f, acc[r]);
                acc[r] = __fmaf_rn(fabsf(u3), 2.0f, acc[r]);
            }
        }
        // exact neg tail (no padding, keeps abs identity valid)
        for (int j = nneg4 + tid; j < nneg; j += TPB) {
            const float n = sneg[j];
            #pragma unroll
            for (int r = 0; r < ROWS; r++)
                acc[r] = __fmaf_rn(fabsf(__fmaf_rn(n, 0.5f, ch[r])), 2.0f, acc[r]);
        }
        #pragma unroll
        for (int r = 0; r < ROWS; r++) accv += acc[r];
    }
    // pos tail rows (< ROWS)
    for (; r0 < r_end; r0++) {
        const float ch0 = __fmaf_rn(spos[r0], -0.5f, 0.5f);
        float a = 0.f;
        for (int j = tid; j < nneg; j += TPB)
            a = __fmaf_rn(fabsf(__fmaf_rn(sneg[j], 0.5f, ch0)), 2.0f, a);
        accv += a;
    }

    // ---- block reduction (fixed order -> deterministic) ----
    #pragma unroll
    for (int o = 16; o > 0; o >>= 1)
        accv += __shfl_down_sync(0xffffffffu, accv, o);
    if (lane == 0) s_red[warp] = accv;
    __syncthreads();
    if (warp == 0) {
        float w = s_red[lane];
        #pragma unroll
        for (int o = 16; o > 0; o >>= 1)
            w += __shfl_down_sync(0xffffffffu, w, o);
        if (lane == 0) g_partial[blockIdx.x] = w;
    }

    // ---- phase 3: last block finalizes ----
    if (tid == 0) {
        __threadfence();
        unsigned int prev = atomicAdd(&g_arrive, 1u);
        s_amlast = (prev == GRID - 1);
    }
    __syncthreads();
    if (!s_amlast) return;
    __threadfence();

    // Sp, Sn in double, fixed strided order (deterministic), 2-way ILP
    double dp0 = 0.0, dp1 = 0.0, dn0 = 0.0, dn1 = 0.0;
    for (int i = tid; i < npos; i += 2 * TPB)           dp0 += (double)spos[i];
    for (int i = tid + TPB; i < npos; i += 2 * TPB)     dp1 += (double)spos[i];
    for (int i = tid; i < nneg; i += 2 * TPB)           dn0 += (double)sneg[i];
    for (int i = tid + TPB; i < nneg; i += 2 * TPB)     dn1 += (double)sneg[i];
    double dp = dp0 + dp1, dn = dn0 + dn1;
    #pragma unroll
    for (int o = 16; o > 0; o >>= 1) {
        dp += __shfl_down_sync(0xffffffffu, dp, o);
        dn += __shfl_down_sync(0xffffffffu, dn, o);
    }
    if (lane == 0) { s_dp[warp] = dp; s_dn[warp] = dn; }
    __syncthreads();
    if (warp == 0) {
        double p = s_dp[lane], n = s_dn[lane];
        double S = 0.0;
        for (int i = lane; i < GRID; i += 32) S += (double)g_partial[i];
        #pragma unroll
        for (int o = 16; o > 0; o >>= 1) {
            p += __shfl_down_sync(0xffffffffu, p, o);
            n += __shfl_down_sync(0xffffffffu, n, o);
            S += __shfl_down_sync(0xffffffffu, S, o);
        }
        if (lane == 0) {
            const double lin   = (double)nneg * ((double)npos - p)
                               + (double)npos * n;            // sum of x over pairs
            const double num   = 0.5 * (lin + S);             // sum of max(0,x)
            const double denom = (double)npos * (double)nneg;
            out[0] = (float)(num / denom);
            g_arrive = 0u;    // reset for next graph replay
        }
    }
}

extern "C" void kernel_launch(void* const* d_in, const int* in_sizes, int n_in,
                              void* d_out, int out_size) {
    const int*   yt = (const int*)d_in[0];
    const float* yp = (const float*)d_in[1];

    const int smem_bytes = N_TOTAL * sizeof(float);     // 64 KB
    cudaFuncSetAttribute(fused_kernel,
                         cudaFuncAttributeMaxDynamicSharedMemorySize, smem_bytes);

    fused_kernel<<<GRID, TPB, smem_bytes>>>(yt, yp, (float*)d_out);
}